// round 11
// baseline (speedup 1.0000x reference)
#include <cuda_runtime.h>
#include <cuda_bf16.h>
#include <math_constants.h>

#define NB 8192
#define HWN 4096   // 64*64
#define THREADS 128
#define FP_SCALE 32768.0f   // 2^15 fixed-point scale (deterministic integer sum)

__device__ unsigned long long g_acc;
__device__ unsigned int g_done;

// 128-bit load, 256B L2 refill granularity (R8's proven win), non-coherent path.
__device__ __forceinline__ float4 ld4_pf(const float4* p) {
    float4 v;
    asm volatile("ld.global.nc.L2::256B.v4.f32 {%0,%1,%2,%3}, [%4];"
                 : "=f"(v.x), "=f"(v.y), "=f"(v.z), "=f"(v.w) : "l"(p));
    return v;
}

__global__ void __launch_bounds__(THREADS, 11)
loss_fused_kernel(const float* __restrict__ x, float* __restrict__ out) {
    const int b = blockIdx.x;
    const int t = threadIdx.x;
    const float4* __restrict__ xp =
        reinterpret_cast<const float4*>(x) + (size_t)b * 1024 + t;

    // Thread-constant geometry: q = it*128 + t
    //   j  = q>>4 = it*8 + (t>>4)    (row)
    //   k0 = (q&15)*4 = (t&15)*4     (constant across iterations!)
    const int   tk = t & 15;
    const int   jb = t >> 4;
    const float k0 = (float)(tk << 2);

    // Front-batch all loads (MLP=8)
    float4 v[8];
    #pragma unroll
    for (int it = 0; it < 8; ++it) v[it] = ld4_pf(&xp[it * THREADS]);

    float s0 = 0.f, sm1 = 0.f, sm2 = 0.f, sj = 0.f, sjj = 0.f;
    float bv = -CUDART_INF_F;
    int   bi = 0x7fffffff;

    #pragma unroll
    for (int it = 0; it < 8; ++it) {
        const float X = v[it].x, Y = v[it].y, Z = v[it].z, W = v[it].w;
        const int   ji = it * 8 + jb;
        const float jf = (float)ji;

        const float ls = (X + Y) + (Z + W);
        const float m1 = fmaf(3.f, W, fmaf(2.f, Z, Y)); // sum c*x_c
        const float m2 = fmaf(9.f, W, fmaf(4.f, Z, Y)); // sum c^2*x_c

        s0  += ls;
        sm1 += m1;
        sm2 += m2;
        sj   = fmaf(jf, ls, sj);
        sjj  = fmaf(jf * jf, ls, sjj);

        // argmax: cheap quad-max, rare update branch; within-thread indices
        // are monotone increasing so strict '>' keeps the first max.
        const float m = fmaxf(fmaxf(X, Y), fmaxf(Z, W));
        if (m > bv) {
            bv = m;
            const int c = (m == X) ? 0 : ((m == Y) ? 1 : ((m == Z) ? 2 : 3));
            bi = (ji << 6) + (tk << 2) + c;
        }
    }

    // Fold thread-constant k0 terms
    float sk = fmaf(k0, s0, sm1);                                  // sum k*x
    float sq = fmaf(k0 * k0, s0, fmaf(2.f * k0, sm1, sm2)) + sjj;  // sum (j^2+k^2)*x

    // ---- warp reduction ----
    #pragma unroll
    for (int off = 16; off > 0; off >>= 1) {
        s0 += __shfl_down_sync(0xffffffffu, s0, off);
        sj += __shfl_down_sync(0xffffffffu, sj, off);
        sk += __shfl_down_sync(0xffffffffu, sk, off);
        sq += __shfl_down_sync(0xffffffffu, sq, off);
        const float ov = __shfl_down_sync(0xffffffffu, bv, off);
        const int   oi = __shfl_down_sync(0xffffffffu, bi, off);
        if (ov > bv || (ov == bv && oi < bi)) { bv = ov; bi = oi; }
    }

    // ---- cross-warp reduction ----
    __shared__ float sh_s0[4], sh_sj[4], sh_sk[4], sh_sq[4], sh_bv[4];
    __shared__ int   sh_bi[4];
    const int wid = t >> 5;
    if ((t & 31) == 0) {
        sh_s0[wid] = s0; sh_sj[wid] = sj; sh_sk[wid] = sk; sh_sq[wid] = sq;
        sh_bv[wid] = bv; sh_bi[wid] = bi;
    }
    __syncthreads();

    if (t == 0) {
        float fs0 = sh_s0[0], fsj = sh_sj[0], fsk = sh_sk[0], fsq = sh_sq[0];
        float fbv = sh_bv[0]; int fbi = sh_bi[0];
        #pragma unroll
        for (int w = 1; w < 4; ++w) {
            fs0 += sh_s0[w]; fsj += sh_sj[w]; fsk += sh_sk[w]; fsq += sh_sq[w];
            const float ov = sh_bv[w]; const int oi = sh_bi[w];
            if (ov > fbv || (ov == fbv && oi < fbi)) { fbv = ov; fbi = oi; }
        }
        const float mx = (float)(fbi >> 6);
        const float my = (float)(fbi & 63);
        const float loss = (mx * mx + my * my) * fs0
                         - 2.f * mx * fsj
                         - 2.f * my * fsk
                         + fsq;

        // Deterministic fixed-point accumulation (integer add is associative)
        const long long q = llrintf(loss * FP_SCALE);
        atomicAdd(&g_acc, (unsigned long long)q);
        __threadfence();
        const unsigned int n = atomicAdd(&g_done, 1u);
        if (n == NB - 1u) {
            const long long tot = (long long)atomicExch(&g_acc, 0ULL);
            g_done = 0;
            out[0] = (float)((double)tot / (double)FP_SCALE);
        }
    }
}

extern "C" void kernel_launch(void* const* d_in, const int* in_sizes, int n_in,
                              void* d_out, int out_size) {
    const float* x = (const float*)d_in[0];
    float* out = (float*)d_out;
    loss_fused_kernel<<<NB, THREADS>>>(x, out);
}

// round 12
// speedup vs baseline: 1.0479x; 1.0479x over previous
#include <cuda_runtime.h>
#include <cuda_bf16.h>
#include <math_constants.h>

#define NB 8192
#define GRID 1024           // 1024 CTAs x 4 warps x 2 samples = 8192 samples
#define THREADS 128
#define FP_SCALE 32768.0

__device__ unsigned long long g_acc;
__device__ unsigned int g_done;

// Packed fp32x2 ops (Blackwell FFMA2 path — PTX-only)
#define ADDX2(d, a, b)    asm("add.rn.f32x2 %0,%1,%2;"    : "=l"(d) : "l"(a), "l"(b))
#define FMAX2(d, a, b, c) asm("fma.rn.f32x2 %0,%1,%2,%3;" : "=l"(d) : "l"(a), "l"(b), "l"(c))
#define PACKX2(d, lo, hi) asm("mov.b64 %0,{%1,%2};"       : "=l"(d) : "f"(lo), "f"(hi))
#define UNPACKX2(lo, hi, d) asm("mov.b64 {%0,%1},%2;"     : "=f"(lo), "=f"(hi) : "l"(d))

// 128-bit load, 256B L2 refill granularity (R8's proven win)
__device__ __forceinline__ float4 ld4_pf(const float4* p) {
    float4 v;
    asm volatile("ld.global.nc.L2::256B.v4.f32 {%0,%1,%2,%3}, [%4];"
                 : "=f"(v.x), "=f"(v.y), "=f"(v.z), "=f"(v.w) : "l"(p));
    return v;
}

__global__ void __launch_bounds__(THREADS, 7)
loss_kernel(const float* __restrict__ x, float* __restrict__ out) {
    const int t = threadIdx.x;
    const int w = t >> 5;
    const int l = t & 31;
    const int warp_g = blockIdx.x * 4 + w;

    __shared__ float wloss[4];

    // lane's base pointer for sample 0; sample 1 is a constant offset away
    const float4* __restrict__ xp0 =
        reinterpret_cast<const float4*>(x) + (size_t)warp_g * 1024 + l;
    const size_t OFF1 = (size_t)4096 * 1024;   // +4096 samples, in float4s

    const unsigned long long C23 = 0x4040000040000000ULL; // (2.0f, 3.0f)
    const unsigned long long C49 = 0x4110000040800000ULL; // (4.0f, 9.0f)

    // packed accumulators (reused for sample 1 after the mid-stream fold)
    unsigned long long s0p = 0, Up = 0, Vp = 0, mp1 = 0, mp2 = 0;
    float sy = 0.f;
    float bv = -CUDART_INF_F;
    int   bi = 0x7fffffff;

    float acc_loss = 0.f;   // lane-0-valid after each fold

    // continuous 64-chunk stream (2 samples x 32 chunks), one 4-deep ring
    // that never drains at the sample boundary.
    float4 buf[4];
    #pragma unroll
    for (int i = 0; i < 4; ++i) buf[i] = ld4_pf(&xp0[i * 32]);

    #pragma unroll
    for (int n = 0; n < 64; ++n) {
        const float4 v = buf[n & 3];

        // issue load for chunk n+4 BEFORE computing chunk n
        if (n < 60) {
            const int nn = n + 4;
            const size_t base = (nn >= 32) ? OFF1 : 0;
            buf[n & 3] = ld4_pf(&xp0[base + (size_t)(nn & 31) * 32]);
        }

        const int c = n & 31;                   // chunk index within sample
        const float X = v.x, Y = v.y, Z = v.z, W = v.w;
        unsigned long long p0, p1, lsp;
        PACKX2(p0, X, Y);
        PACKX2(p1, Z, W);
        ADDX2(lsp, p0, p1);                     // (X+Z, Y+W)
        ADDX2(s0p, s0p, lsp);                   // running sum
        ADDX2(Up,  Up,  s0p);                   // prefix -> c-moment
        ADDX2(Vp,  Vp,  Up);                    // -> c^2-moment
        FMAX2(mp1, p1, C23, mp1);               // 2Z + 3W
        FMAX2(mp2, p1, C49, mp2);               // 4Z + 9W
        sy += Y;

        const float m = fmaxf(fmaxf(X, Y), fmaxf(Z, W));
        if (m > bv) {                           // first-max: strict '>', c ascending
            bv = m;
            const int cc = (m == X) ? 0 : ((m == Y) ? 1 : ((m == Z) ? 2 : 3));
            bi = ((c * 32 + l) << 2) + cc;
        }

        // ---- sample boundary: fold + reduce while sample-1 loads fly ----
        if (n == 31 || n == 63) {
            float s0lo, s0hi, Ulo, Uhi, Vlo, Vhi, m1lo, m1hi, m2lo, m2hi;
            UNPACKX2(s0lo, s0hi, s0p);
            UNPACKX2(Ulo, Uhi, Up);
            UNPACKX2(Vlo, Vhi, Vp);
            UNPACKX2(m1lo, m1hi, mp1);
            UNPACKX2(m2lo, m2hi, mp2);

            float s0 = s0lo + s0hi;
            const float cU = Ulo + Uhi;
            const float cV = Vlo + Vhi;
            // Sum c*ls = 32*s0 - U ;  Sum c^2*ls = 1024*s0 - 65*U + 2*V
            const float sc1 = fmaf(32.f, s0, -cU);
            const float sc2 = fmaf(1024.f, s0, fmaf(-65.f, cU, 2.f * cV));
            // j = 2c + jh
            const float jh = (float)(l >> 4);
            float sj  = fmaf(2.f, sc1, jh * s0);
            float sjj = fmaf(4.f, sc2, fmaf(4.f * jh, sc1, jh * s0)); // jh^2 == jh
            // k = k0 + cc  (k0 thread-constant)
            const float m1 = sy + m1lo + m1hi;
            const float m2 = sy + m2lo + m2hi;
            const float k0 = (float)((l & 15) << 2);
            float sk  = fmaf(k0, s0, m1);
            const float skk = fmaf(k0 * k0, s0, fmaf(2.f * k0, m1, m2));
            float sq = sjj + skk;

            #pragma unroll
            for (int off = 16; off > 0; off >>= 1) {
                s0 += __shfl_down_sync(0xffffffffu, s0, off);
                sj += __shfl_down_sync(0xffffffffu, sj, off);
                sk += __shfl_down_sync(0xffffffffu, sk, off);
                sq += __shfl_down_sync(0xffffffffu, sq, off);
                const float ov = __shfl_down_sync(0xffffffffu, bv, off);
                const int   oi = __shfl_down_sync(0xffffffffu, bi, off);
                if (ov > bv || (ov == bv && oi < bi)) { bv = ov; bi = oi; }
            }

            if (l == 0) {
                const float mx = (float)(bi >> 6);
                const float my = (float)(bi & 63);
                acc_loss += (mx * mx + my * my) * s0
                          - 2.f * mx * sj - 2.f * my * sk + sq;
            }

            // reset accumulators for sample 1
            s0p = 0; Up = 0; Vp = 0; mp1 = 0; mp2 = 0;
            sy = 0.f; bv = -CUDART_INF_F; bi = 0x7fffffff;
        }
    }

    if (l == 0) wloss[w] = acc_loss;
    __syncthreads();

    if (t == 0) {
        const double tot = (double)wloss[0] + (double)wloss[1]
                         + (double)wloss[2] + (double)wloss[3];
        const long long q = llrint(tot * FP_SCALE);
        atomicAdd(&g_acc, (unsigned long long)q);
        __threadfence();
        const unsigned int n = atomicAdd(&g_done, 1u);
        if (n == GRID - 1u) {
            const long long totq = (long long)atomicExch(&g_acc, 0ULL);
            g_done = 0;
            out[0] = (float)((double)totq / FP_SCALE);
        }
    }
}

extern "C" void kernel_launch(void* const* d_in, const int* in_sizes, int n_in,
                              void* d_out, int out_size) {
    const float* x = (const float*)d_in[0];
    float* out = (float*)d_out;
    loss_kernel<<<GRID, THREADS>>>(x, out);
}